// round 2
// baseline (speedup 1.0000x reference)
#include <cuda_runtime.h>
#include <cuda_bf16.h>
#include <math.h>

// PCL loss reduction:
//   valid = target != -1
//   p     = (target==0) ? input[i*C + 0] : pc_input[cluster[i]]
//   loss  = sum(valid * (-weight * log(max(p, 1e-12)))) / max(sum(valid), 1)
//
// N = 2,097,152, C = 21, NUM_CLUSTERS = 4096. Output: single float.

#define C_CLASSES 21
#define EPS 1e-12f

__device__ float g_sum;
__device__ unsigned int g_cnt;

__global__ void pcl_init() {
    g_sum = 0.0f;
    g_cnt = 0u;
}

__device__ __forceinline__ void pcl_one(int t, int c, float w, int idx,
                                        const float* __restrict__ input,
                                        const float* __restrict__ pc,
                                        float& lsum, unsigned int& lcnt) {
    if (t != -1) {
        lcnt++;
        float p;
        if (t == 0) {
            // strided gather: only ~1/21 of lanes take this path -> saves DRAM sectors
            p = __ldg(input + (long long)idx * C_CLASSES);
        } else {
            p = __ldg(pc + c);          // 16 KB table, L1/L2 resident
        }
        lsum += w * __logf(fmaxf(p, EPS));   // accumulate +w*log, negate at the end
    }
}

__global__ void __launch_bounds__(256, 8)
pcl_main(const float* __restrict__ input,
         const float* __restrict__ weight,
         const float* __restrict__ pc,
         const int* __restrict__ target,
         const int* __restrict__ cluster,
         int n) {
    float lsum = 0.0f;
    unsigned int lcnt = 0u;

    const int stride = gridDim.x * blockDim.x * 4;
    for (int i = (blockIdx.x * blockDim.x + threadIdx.x) * 4; i < n; i += stride) {
        if (i + 3 < n) {
            int4   t4 = *reinterpret_cast<const int4*>(target + i);
            int4   c4 = *reinterpret_cast<const int4*>(cluster + i);
            float4 w4 = *reinterpret_cast<const float4*>(weight + i);
            pcl_one(t4.x, c4.x, w4.x, i + 0, input, pc, lsum, lcnt);
            pcl_one(t4.y, c4.y, w4.y, i + 1, input, pc, lsum, lcnt);
            pcl_one(t4.z, c4.z, w4.z, i + 2, input, pc, lsum, lcnt);
            pcl_one(t4.w, c4.w, w4.w, i + 3, input, pc, lsum, lcnt);
        } else {
            for (int k = i; k < n; k++) {
                pcl_one(target[k], cluster[k], weight[k], k, input, pc, lsum, lcnt);
            }
        }
    }

    // warp reduction
    #pragma unroll
    for (int off = 16; off > 0; off >>= 1) {
        lsum += __shfl_xor_sync(0xFFFFFFFFu, lsum, off);
        lcnt += __shfl_xor_sync(0xFFFFFFFFu, lcnt, off);
    }

    // block reduction via shared memory (8 warps)
    __shared__ float s_sum[8];
    __shared__ unsigned int s_cnt[8];
    int wid = threadIdx.x >> 5;
    int lid = threadIdx.x & 31;
    if (lid == 0) { s_sum[wid] = lsum; s_cnt[wid] = lcnt; }
    __syncthreads();
    if (wid == 0) {
        lsum = (lid < 8) ? s_sum[lid] : 0.0f;
        lcnt = (lid < 8) ? s_cnt[lid] : 0u;
        #pragma unroll
        for (int off = 4; off > 0; off >>= 1) {
            lsum += __shfl_xor_sync(0xFFFFFFFFu, lsum, off);
            lcnt += __shfl_xor_sync(0xFFFFFFFFu, lcnt, off);
        }
        if (lid == 0) {
            atomicAdd(&g_sum, lsum);
            atomicAdd(&g_cnt, lcnt);
        }
    }
}

__global__ void pcl_final(float* __restrict__ out) {
    float nv = fmaxf((float)g_cnt, 1.0f);
    *out = -g_sum / nv;   // negate the +w*log accumulation
}

extern "C" void kernel_launch(void* const* d_in, const int* in_sizes, int n_in,
                              void* d_out, int out_size) {
    const float* input   = (const float*)d_in[0];   // [N, 21]
    const float* weight  = (const float*)d_in[1];   // [N]
    const float* pc      = (const float*)d_in[2];   // [4096]
    const int*   target  = (const int*)d_in[3];     // [N] int32
    const int*   cluster = (const int*)d_in[4];     // [N] int32
    float* out = (float*)d_out;

    int n = in_sizes[1];   // weight element count == N

    pcl_init<<<1, 1>>>();
    int threads = 256;
    int quads_per_block = threads * 4;
    int blocks = (n + quads_per_block - 1) / quads_per_block;
    if (blocks > 2048) blocks = 2048;
    if (blocks < 1) blocks = 1;
    pcl_main<<<blocks, threads>>>(input, weight, pc, target, cluster, n);
    pcl_final<<<1, 1>>>(out);
}